// round 3
// baseline (speedup 1.0000x reference)
#include <cuda_runtime.h>
#include <math.h>
#include <stdint.h>

#define B_ 4
#define N_ 8192
#define D_ 1024
#define H_ 8
#define DH_ 64
#define HID_ 512
#define WIN_ 128
#define NW_ 64
#define NQ_ 1024
#define NKV_ 2048
#define BN_ (B_*N_)

// ---------------- scratch (device globals; no allocations allowed) ----------------
__device__ float g_xn  [(long long)BN_*D_];        // rmsnorm(x)*gamma_light
__device__ float g_ql  [(long long)BN_*HID_];      // light q proj
__device__ float g_kvl [(long long)BN_*2*HID_];    // light kv proj
__device__ float g_aol [(long long)BN_*HID_];      // light attn out
__device__ float g_s   [2*B_*N_];                  // routing logits [route][b][n]
__device__ unsigned long long g_keys[8*N_];        // sort buffers
__device__ int   g_idx [2*B_*NKV_];                // selected indices [route][b][j]
__device__ float g_xqn [B_*NQ_*D_];
__device__ float g_ctxn[B_*NKV_*D_];
__device__ float g_qh  [B_*NQ_*HID_];
__device__ float g_kvh [B_*NKV_*2*HID_];
__device__ float g_aoh [B_*NQ_*HID_];
__device__ float g_hout[B_*NQ_*D_];
__device__ float g_wkvT[D_*2*HID_];

// ---------------- helpers ----------------
__device__ __forceinline__ float warp_max(float v){
    #pragma unroll
    for (int o=16;o;o>>=1) v = fmaxf(v, __shfl_xor_sync(0xffffffffu, v, o));
    return v;
}
__device__ __forceinline__ float warp_sum(float v){
    #pragma unroll
    for (int o=16;o;o>>=1) v += __shfl_xor_sync(0xffffffffu, v, o);
    return v;
}
__device__ __forceinline__ uint32_t f2tf(float f){
    uint32_t u;
    asm("cvt.rna.tf32.f32 %0, %1;" : "=r"(u) : "f"(f));
    return u;
}

// ---------------- 1. rmsnorm(x)*gamma_light + routing logits ----------------
__global__ __launch_bounds__(256) void rmsnorm_route_kernel(
    const float* __restrict__ x, const float* __restrict__ gamma,
    const float* __restrict__ tq, const float* __restrict__ tkv,
    float* __restrict__ xn, float* __restrict__ sarr)
{
    long long row = blockIdx.x;
    const float* xr = x + row*D_;
    int t = threadIdx.x;
    float xv[4]; float ss=0.f, dq=0.f, dk=0.f;
    #pragma unroll
    for (int j=0;j<4;j++){
        int i = t + j*256;
        float v = xr[i]; xv[j]=v;
        ss = fmaf(v,v,ss); dq = fmaf(v,tq[i],dq); dk = fmaf(v,tkv[i],dk);
    }
    __shared__ float sred[3][8];
    __shared__ float bres[3];
    ss = warp_sum(ss); dq = warp_sum(dq); dk = warp_sum(dk);
    int w = t>>5, lane = t&31;
    if (lane==0){ sred[0][w]=ss; sred[1][w]=dq; sred[2][w]=dk; }
    __syncthreads();
    if (w==0){
        float a = lane<8 ? sred[0][lane] : 0.f;
        float b = lane<8 ? sred[1][lane] : 0.f;
        float c = lane<8 ? sred[2][lane] : 0.f;
        a = warp_sum(a); b = warp_sum(b); c = warp_sum(c);
        if (lane==0){ bres[0]=a; bres[1]=b; bres[2]=c; }
    }
    __syncthreads();
    float norm = fmaxf(sqrtf(bres[0]), 1e-12f);
    float inv = 32.0f / norm;
    float* xo = xn + row*D_;
    #pragma unroll
    for (int j=0;j<4;j++){
        int i = t + j*256;
        xo[i] = xv[j]*inv*gamma[i];
    }
    if (t==0){
        int b = (int)(row >> 13);
        int n = (int)(row & (N_-1));
        sarr[(0*B_ + b)*N_ + n] = bres[1];
        sarr[(1*B_ + b)*N_ + n] = bres[2];
    }
}

// ---------------- 2. coor_descent (50 iters) + exact-tie top-k selection ----------------
__global__ __launch_bounds__(1024) void route_select_kernel(
    const float* __restrict__ sarr, unsigned long long* __restrict__ keysbuf,
    int* __restrict__ idxbuf)
{
    int p = blockIdx.x;            // 0..7 : route*4 + b
    int route = p >> 2, b = p & 3;
    const float* s = sarr + (route*B_ + b)*N_;
    unsigned long long* keys = keysbuf + (long long)p*N_;
    float logk = logf(route==0 ? 1152.0f : 2304.0f);
    int t = threadIdx.x;
    float sl[8], bl[8];
    #pragma unroll
    for (int j=0;j<8;j++){ sl[j] = s[t*8+j]; bl[j] = -sl[j]; }
    __shared__ float sred[32];
    __shared__ float bresM, bresS;
    int w = t>>5, lane = t&31;
    float a = 0.f;
    for (int it=0; it<50; it++){
        float m = -INFINITY;
        #pragma unroll
        for (int j=0;j<8;j++) m = fmaxf(m, sl[j]+bl[j]);
        m = warp_max(m);
        if (lane==0) sred[w]=m;
        __syncthreads();
        if (w==0){ float z = warp_max(sred[lane]); if (lane==0) bresM = z; }
        __syncthreads();
        m = bresM;
        float sum = 0.f;
        #pragma unroll
        for (int j=0;j<8;j++) sum += expf(sl[j]+bl[j]-m);
        sum = warp_sum(sum);
        if (lane==0) sred[w]=sum;
        __syncthreads();
        if (w==0){ float z = warp_sum(sred[lane]); if (lane==0) bresS = z; }
        __syncthreads();
        a = logk - (logf(bresS) + m);
        #pragma unroll
        for (int j=0;j<8;j++) bl[j] = -fmaxf(sl[j]+a, 0.f);
    }
    // scores: saturated -> exactly 1.0f (matches jax: b recomputed with final a,
    // so (s+a)+b == 0 exactly). unsaturated -> exp(s+a).
    #pragma unroll
    for (int j=0;j<8;j++){
        int i = t*8+j;
        float sa = sl[j]+a;
        float val = (sa > 0.f) ? 1.0f : expf(sa);
        unsigned int vb = __float_as_uint(val);   // val >= 0 -> bits monotone
        keys[i] = ((unsigned long long)vb << 32) |
                  (unsigned long long)(0xffffffffu - (unsigned)i);
    }
    __syncthreads();
    // bitonic sort ascending in gmem (single block, 8192 keys)
    for (unsigned size=2; size<=N_; size<<=1){
        for (unsigned stride=size>>1; stride>0; stride>>=1){
            __syncthreads();
            for (unsigned q=t; q<N_/2; q+=1024){
                unsigned pos = 2*q - (q & (stride-1));
                unsigned par = pos + stride;
                bool asc = ((pos & size) == 0);
                unsigned long long a0=keys[pos], a1=keys[par];
                if ((a0 > a1) == asc){ keys[pos]=a1; keys[par]=a0; }
            }
        }
    }
    __syncthreads();
    int K = (route==0) ? NQ_ : NKV_;
    int* sel = idxbuf + (route*B_ + b)*NKV_;
    for (int j=t; j<K; j+=1024)
        sel[j] = (int)(0xffffffffu - (unsigned)(keys[N_-K+j] & 0xffffffffu));
}

// ---------------- 3. gather + rmsnorm (heavy branch) ----------------
__global__ __launch_bounds__(256) void gather_norm_kernel(
    const float* __restrict__ x, const float* __restrict__ gamma,
    const int* __restrict__ idxbuf, int route, int count, float* __restrict__ dst)
{
    int gi = blockIdx.x;
    int b = gi / count, j = gi % count;
    int rowidx = idxbuf[(route*B_ + b)*NKV_ + j];
    const float* xr = x + ((long long)b*N_ + rowidx)*D_;
    float* dr = dst + (long long)gi*D_;
    int t = threadIdx.x;
    float xv[4]; float ss=0.f;
    #pragma unroll
    for (int j4=0;j4<4;j4++){
        int i = t + j4*256;
        float v = xr[i]; xv[j4]=v; ss = fmaf(v,v,ss);
    }
    __shared__ float sred[8];
    __shared__ float bres;
    ss = warp_sum(ss);
    int w=t>>5, lane=t&31;
    if (lane==0) sred[w]=ss;
    __syncthreads();
    if (w==0){ float z = lane<8? sred[lane]:0.f; z = warp_sum(z); if (lane==0) bres=z; }
    __syncthreads();
    float inv = 32.0f / fmaxf(sqrtf(bres), 1e-12f);
    #pragma unroll
    for (int j4=0;j4<4;j4++){
        int i = t + j4*256;
        dr[i] = xv[j4]*inv*gamma[i];
    }
}

// ---------------- 4. tf32 tensor-core GEMM: C[M,N] = A[M,K] @ B[K,N] ----------------
// fp32 in/out, tf32 mma.sync.m16n8k8, fp32 accumulate.
// BM=128, BN=128, BK=32, 256 threads = 8 warps (4 along M x 2 along N).
// assumes M%128==0, N%128==0, K%32==0
__global__ __launch_bounds__(256) void tf32gemm_kernel(
    const float* __restrict__ A, const float* __restrict__ Bm, float* __restrict__ C,
    int M, int N, int K)
{
    __shared__ float As[128][36];   // [m][k], pad->frag loads conflict-free (bank=4m+k)
    __shared__ float Bs[32][132];   // [k][n], float4-aligned rows
    int tid = threadIdx.x;
    int m0 = blockIdx.y*128, n0 = blockIdx.x*128;
    int warp = tid>>5, lane = tid&31;
    int wm = (warp&3)*32;          // warp tile: 32 rows
    int wn = (warp>>2)*64;         //            64 cols
    int g = lane>>2, tig = lane&3;

    int arow = tid>>1, acol = (tid&1)*16;   // A gmem->smem: 2 thr/row, 16 floats each
    int brow = tid>>3, bcol = (tid&7)*16;   // B gmem->smem: 8 thr/row

    float c[2][8][4];
    #pragma unroll
    for (int t=0;t<2;t++)
        #pragma unroll
        for (int u=0;u<8;u++)
            #pragma unroll
            for (int v=0;v<4;v++) c[t][u][v]=0.f;

    for (int k0=0; k0<K; k0+=32){
        float4 av[4], bv[4];
        #pragma unroll
        for (int i=0;i<4;i++)
            av[i] = *(const float4*)(A + (long long)(m0+arow)*K + k0 + acol + 4*i);
        #pragma unroll
        for (int i=0;i<4;i++)
            bv[i] = *(const float4*)(Bm + (long long)(k0+brow)*N + n0 + bcol + 4*i);
        __syncthreads();
        #pragma unroll
        for (int i=0;i<4;i++) *(float4*)&As[arow][acol+4*i] = av[i];
        #pragma unroll
        for (int i=0;i<4;i++) *(float4*)&Bs[brow][bcol+4*i] = bv[i];
        __syncthreads();
        #pragma unroll
        for (int ks=0; ks<4; ks++){
            int kb = ks*8;
            uint32_t a[2][4], b[8][2];
            #pragma unroll
            for (int t=0;t<2;t++){
                int mr = wm + t*16 + g;
                a[t][0] = f2tf(As[mr  ][kb+tig  ]);
                a[t][1] = f2tf(As[mr+8][kb+tig  ]);
                a[t][2] = f2tf(As[mr  ][kb+tig+4]);
                a[t][3] = f2tf(As[mr+8][kb+tig+4]);
            }
            #pragma unroll
            for (int u=0;u<8;u++){
                int nc = wn + u*8 + g;
                b[u][0] = f2tf(Bs[kb+tig  ][nc]);
                b[u][1] = f2tf(Bs[kb+tig+4][nc]);
            }
            #pragma unroll
            for (int t=0;t<2;t++)
                #pragma unroll
                for (int u=0;u<8;u++)
                    asm volatile(
                        "mma.sync.aligned.m16n8k8.row.col.f32.tf32.tf32.f32 "
                        "{%0,%1,%2,%3},{%4,%5,%6,%7},{%8,%9},{%0,%1,%2,%3};"
                        : "+f"(c[t][u][0]), "+f"(c[t][u][1]),
                          "+f"(c[t][u][2]), "+f"(c[t][u][3])
                        : "r"(a[t][0]), "r"(a[t][1]), "r"(a[t][2]), "r"(a[t][3]),
                          "r"(b[u][0]), "r"(b[u][1]));
        }
    }
    #pragma unroll
    for (int t=0;t<2;t++){
        long long mr = m0 + wm + t*16 + g;
        #pragma unroll
        for (int u=0;u<8;u++){
            long long nc = n0 + wn + u*8 + 2*tig;
            C[mr*N + nc]       = c[t][u][0];
            C[mr*N + nc + 1]   = c[t][u][1];
            C[(mr+8)*N + nc]   = c[t][u][2];
            C[(mr+8)*N + nc+1] = c[t][u][3];
        }
    }
}

// ---------------- 5. light windowed attention ----------------
__global__ __launch_bounds__(128) void attn_win_kernel(
    const float* __restrict__ Q, const float* __restrict__ KV, float* __restrict__ O)
{
    __shared__ float ks[32][65], vs[32][65];
    int bid = blockIdx.x;              // b*512 + w*8 + h
    int h = bid & 7;
    int w = (bid >> 3) & 63;
    int b = bid >> 9;
    int i = threadIdx.x;               // q row in window
    long long base_row = (long long)b*N_ + (long long)w*WIN_;
    const float* qp = Q + (base_row + i)*HID_ + h*DH_;
    float qv[64];
    #pragma unroll
    for (int d=0;d<64;d++) qv[d] = qp[d]*0.125f;
    float m = -INFINITY, l = 0.f, acc[64];
    #pragma unroll
    for (int d=0;d<64;d++) acc[d]=0.f;
    for (int t0=0; t0<WIN_; t0+=32){
        __syncthreads();
        {
            int r = i >> 2, c0 = (i & 3)*16;
            const float* kp = KV + (base_row + t0 + r)*(2*HID_) + h*DH_;
            const float* vp = kp + HID_;
            #pragma unroll
            for (int c=0;c<16;c++){ ks[r][c0+c]=kp[c0+c]; vs[r][c0+c]=vp[c0+c]; }
        }
        __syncthreads();
        float sj[32], tmx = -INFINITY;
        #pragma unroll
        for (int j=0;j<32;j++){
            float s = 0.f;
            #pragma unroll
            for (int d=0;d<64;d++) s = fmaf(qv[d], ks[j][d], s);
            sj[j]=s; tmx = fmaxf(tmx, s);
        }
        float mn = fmaxf(m, tmx);
        float corr = expf(m - mn);
        l *= corr;
        #pragma unroll
        for (int d=0;d<64;d++) acc[d]*=corr;
        #pragma unroll
        for (int j=0;j<32;j++){
            float pexp = expf(sj[j]-mn);
            l += pexp;
            #pragma unroll
            for (int d=0;d<64;d++) acc[d] = fmaf(pexp, vs[j][d], acc[d]);
        }
        m = mn;
    }
    float invl = 1.f/l;
    float* op = O + (base_row + i)*HID_ + h*DH_;
    #pragma unroll
    for (int d=0;d<64;d++) op[d] = acc[d]*invl;
}

// ---------------- 6. heavy attention (NQ x NKV per (b,h)) ----------------
__global__ __launch_bounds__(128) void attn_heavy_kernel(
    const float* __restrict__ Q, const float* __restrict__ KV, float* __restrict__ O)
{
    __shared__ float ks[32][65], vs[32][65];
    int bid = blockIdx.x;              // b*64 + h*8 + qt
    int qt = bid & 7;
    int h  = (bid >> 3) & 7;
    int b  = bid >> 6;
    int i = threadIdx.x;
    int qrow = qt*128 + i;
    const float* qp = Q + ((long long)b*NQ_ + qrow)*HID_ + h*DH_;
    float qv[64];
    #pragma unroll
    for (int d=0;d<64;d++) qv[d] = qp[d]*0.125f;
    float m = -INFINITY, l = 0.f, acc[64];
    #pragma unroll
    for (int d=0;d<64;d++) acc[d]=0.f;
    for (int t0=0; t0<NKV_; t0+=32){
        __syncthreads();
        {
            int r = i >> 2, c0 = (i & 3)*16;
            const float* kp = KV + ((long long)b*NKV_ + t0 + r)*(2*HID_) + h*128;
            const float* vp = kp + 64;
            #pragma unroll
            for (int c=0;c<16;c++){ ks[r][c0+c]=kp[c0+c]; vs[r][c0+c]=vp[c0+c]; }
        }
        __syncthreads();
        float sj[32], tmx = -INFINITY;
        #pragma unroll
        for (int j=0;j<32;j++){
            float s = 0.f;
            #pragma unroll
            for (int d=0;d<64;d++) s = fmaf(qv[d], ks[j][d], s);
            sj[j]=s; tmx = fmaxf(tmx, s);
        }
        float mn = fmaxf(m, tmx);
        float corr = expf(m - mn);
        l *= corr;
        #pragma unroll
        for (int d=0;d<64;d++) acc[d]*=corr;
        #pragma unroll
        for (int j=0;j<32;j++){
            float pexp = expf(sj[j]-mn);
            l += pexp;
            #pragma unroll
            for (int d=0;d<64;d++) acc[d] = fmaf(pexp, vs[j][d], acc[d]);
        }
        m = mn;
    }
    float invl = 1.f/l;
    float* op = O + ((long long)b*NQ_ + qrow)*HID_ + h*DH_;
    #pragma unroll
    for (int d=0;d<64;d++) op[d] = acc[d]*invl;
}

// ---------------- 7. transpose 1024x1024 (wkv_heavy [out,in] -> [in,out]) ----------------
__global__ void transpose1024_kernel(const float* __restrict__ in, float* __restrict__ out)
{
    __shared__ float tile[32][33];
    int x = blockIdx.x*32 + threadIdx.x;
    int y = blockIdx.y*32 + threadIdx.y;
    tile[threadIdx.y][threadIdx.x] = in[(long long)y*1024 + x];
    __syncthreads();
    int x2 = blockIdx.y*32 + threadIdx.x;
    int y2 = blockIdx.x*32 + threadIdx.y;
    out[(long long)y2*1024 + x2] = tile[threadIdx.x][threadIdx.y];
}

// ---------------- 8. scatter-add heavy rows into output ----------------
__global__ __launch_bounds__(256) void scatter_add_kernel(
    float* __restrict__ out, const int* __restrict__ idxbuf, const float* __restrict__ hout)
{
    int gi = blockIdx.x;               // b*NQ + j
    int b = gi >> 10, j = gi & 1023;
    int row = idxbuf[(0*B_ + b)*NKV_ + j];
    float* o = out + ((long long)b*N_ + row)*D_;
    const float* hs = hout + (long long)gi*D_;
    for (int c=threadIdx.x; c<D_; c+=256) o[c] += hs[c];
}

// ---------------- launch ----------------
extern "C" void kernel_launch(void* const* d_in, const int* in_sizes, int n_in,
                              void* d_out, int out_size)
{
    const float* x       = (const float*)d_in[0];
    const float* gamma_l = (const float*)d_in[1];
    const float* wq_l    = (const float*)d_in[2];
    const float* wkv_l   = (const float*)d_in[3];
    const float* wo_l    = (const float*)d_in[4];
    const float* tq      = (const float*)d_in[5];
    const float* tkv     = (const float*)d_in[6];
    const float* gamma_h = (const float*)d_in[7];
    const float* wq_h    = (const float*)d_in[8];
    const float* wkv_h   = (const float*)d_in[9];
    const float* wo_h    = (const float*)d_in[10];
    float* out = (float*)d_out;

    void *p;
    cudaGetSymbolAddress(&p, g_xn);   float* xn   = (float*)p;
    cudaGetSymbolAddress(&p, g_ql);   float* ql   = (float*)p;
    cudaGetSymbolAddress(&p, g_kvl);  float* kvl  = (float*)p;
    cudaGetSymbolAddress(&p, g_aol);  float* aol  = (float*)p;
    cudaGetSymbolAddress(&p, g_s);    float* sarr = (float*)p;
    cudaGetSymbolAddress(&p, g_keys); unsigned long long* keys = (unsigned long long*)p;
    cudaGetSymbolAddress(&p, g_idx);  int* idx    = (int*)p;
    cudaGetSymbolAddress(&p, g_xqn);  float* xqn  = (float*)p;
    cudaGetSymbolAddress(&p, g_ctxn); float* ctxn = (float*)p;
    cudaGetSymbolAddress(&p, g_qh);   float* qh   = (float*)p;
    cudaGetSymbolAddress(&p, g_kvh);  float* kvh  = (float*)p;
    cudaGetSymbolAddress(&p, g_aoh);  float* aoh  = (float*)p;
    cudaGetSymbolAddress(&p, g_hout); float* hout = (float*)p;
    cudaGetSymbolAddress(&p, g_wkvT); float* wkvT = (float*)p;

    // light path
    rmsnorm_route_kernel<<<BN_, 256>>>(x, gamma_l, tq, tkv, xn, sarr);
    tf32gemm_kernel<<<dim3(HID_/128, BN_/128), 256>>>(xn, wq_l,  ql,  BN_, HID_,   D_);
    tf32gemm_kernel<<<dim3(1024/128, BN_/128), 256>>>(xn, wkv_l, kvl, BN_, 2*HID_, D_);
    attn_win_kernel<<<B_*NW_*H_, 128>>>(ql, kvl, aol);
    tf32gemm_kernel<<<dim3(D_/128, BN_/128), 256>>>(aol, wo_l, out, BN_, D_, HID_);

    // routing
    route_select_kernel<<<8, 1024>>>(sarr, keys, idx);

    // heavy path
    gather_norm_kernel<<<B_*NQ_,  256>>>(x, gamma_h, idx, 0, NQ_,  xqn);
    gather_norm_kernel<<<B_*NKV_, 256>>>(x, gamma_h, idx, 1, NKV_, ctxn);
    transpose1024_kernel<<<dim3(32,32), dim3(32,32)>>>(wkv_h, wkvT);
    tf32gemm_kernel<<<dim3(HID_/128, (B_*NQ_)/128),  256>>>(xqn,  wq_h, qh,  B_*NQ_,  HID_,   D_);
    tf32gemm_kernel<<<dim3(1024/128, (B_*NKV_)/128), 256>>>(ctxn, wkvT, kvh, B_*NKV_, 2*HID_, D_);
    attn_heavy_kernel<<<B_*H_*(NQ_/128), 128>>>(qh, kvh, aoh);
    tf32gemm_kernel<<<dim3(D_/128, (B_*NQ_)/128), 256>>>(aoh, wo_h, hout, B_*NQ_, D_, HID_);
    scatter_add_kernel<<<B_*NQ_, 256>>>(out, idx, hout);
}

// round 5
// speedup vs baseline: 1.0531x; 1.0531x over previous
#include <cuda_runtime.h>
#include <math.h>
#include <stdint.h>

#define B_ 4
#define N_ 8192
#define D_ 1024
#define H_ 8
#define DH_ 64
#define HID_ 512
#define WIN_ 128
#define NW_ 64
#define NQ_ 1024
#define NKV_ 2048
#define BN_ (B_*N_)

// ---------------- scratch (device globals; no allocations allowed) ----------------
__device__ float g_xn  [(long long)BN_*D_];
__device__ float g_ql  [(long long)BN_*HID_];
__device__ float g_kvl [(long long)BN_*2*HID_];
__device__ float g_aol [(long long)BN_*HID_];
__device__ float g_s   [2*B_*N_];
__device__ unsigned long long g_keys[8*N_];
__device__ int   g_idx [2*B_*NKV_];
__device__ float g_xqn [B_*NQ_*D_];
__device__ float g_ctxn[B_*NKV_*D_];
__device__ float g_qh  [B_*NQ_*HID_];
__device__ float g_kvh [B_*NKV_*2*HID_];
__device__ float g_aoh [B_*NQ_*HID_];
__device__ float g_hout[B_*NQ_*D_];
__device__ float g_wkvT[D_*2*HID_];

// ---------------- helpers ----------------
__device__ __forceinline__ float warp_max(float v){
    #pragma unroll
    for (int o=16;o;o>>=1) v = fmaxf(v, __shfl_xor_sync(0xffffffffu, v, o));
    return v;
}
__device__ __forceinline__ float warp_sum(float v){
    #pragma unroll
    for (int o=16;o;o>>=1) v += __shfl_xor_sync(0xffffffffu, v, o);
    return v;
}
__device__ __forceinline__ uint32_t f2tf(float f){
    uint32_t u;
    asm("cvt.rna.tf32.f32 %0, %1;" : "=r"(u) : "f"(f));
    return u;
}

// ---------------- 1. rmsnorm(x)*gamma_light + routing logits ----------------
__global__ __launch_bounds__(256) void rmsnorm_route_kernel(
    const float* __restrict__ x, const float* __restrict__ gamma,
    const float* __restrict__ tq, const float* __restrict__ tkv,
    float* __restrict__ xn, float* __restrict__ sarr)
{
    long long row = blockIdx.x;
    const float* xr = x + row*D_;
    int t = threadIdx.x;
    float xv[4]; float ss=0.f, dq=0.f, dk=0.f;
    #pragma unroll
    for (int j=0;j<4;j++){
        int i = t + j*256;
        float v = xr[i]; xv[j]=v;
        ss = fmaf(v,v,ss); dq = fmaf(v,tq[i],dq); dk = fmaf(v,tkv[i],dk);
    }
    __shared__ float sred[3][8];
    __shared__ float bres[3];
    ss = warp_sum(ss); dq = warp_sum(dq); dk = warp_sum(dk);
    int w = t>>5, lane = t&31;
    if (lane==0){ sred[0][w]=ss; sred[1][w]=dq; sred[2][w]=dk; }
    __syncthreads();
    if (w==0){
        float a = lane<8 ? sred[0][lane] : 0.f;
        float b = lane<8 ? sred[1][lane] : 0.f;
        float c = lane<8 ? sred[2][lane] : 0.f;
        a = warp_sum(a); b = warp_sum(b); c = warp_sum(c);
        if (lane==0){ bres[0]=a; bres[1]=b; bres[2]=c; }
    }
    __syncthreads();
    float norm = fmaxf(sqrtf(bres[0]), 1e-12f);
    float inv = 32.0f / norm;
    float* xo = xn + row*D_;
    #pragma unroll
    for (int j=0;j<4;j++){
        int i = t + j*256;
        xo[i] = xv[j]*inv*gamma[i];
    }
    if (t==0){
        int b = (int)(row >> 13);
        int n = (int)(row & (N_-1));
        sarr[(0*B_ + b)*N_ + n] = bres[1];
        sarr[(1*B_ + b)*N_ + n] = bres[2];
    }
}

// ---------------- 2. coor_descent (50 iters) + exact-tie top-k selection ----------------
__global__ __launch_bounds__(1024) void route_select_kernel(
    const float* __restrict__ sarr, unsigned long long* __restrict__ keysbuf,
    int* __restrict__ idxbuf)
{
    int p = blockIdx.x;            // 0..7 : route*4 + b
    int route = p >> 2, b = p & 3;
    const float* s = sarr + (route*B_ + b)*N_;
    unsigned long long* keys = keysbuf + (long long)p*N_;
    float logk = logf(route==0 ? 1152.0f : 2304.0f);
    int t = threadIdx.x;
    float sl[8], bl[8];
    #pragma unroll
    for (int j=0;j<8;j++){ sl[j] = s[t*8+j]; bl[j] = -sl[j]; }
    __shared__ float sred[32];
    __shared__ float bresM, bresS;
    int w = t>>5, lane = t&31;
    float a = 0.f;
    for (int it=0; it<50; it++){
        float m = -INFINITY;
        #pragma unroll
        for (int j=0;j<8;j++) m = fmaxf(m, sl[j]+bl[j]);
        m = warp_max(m);
        if (lane==0) sred[w]=m;
        __syncthreads();
        if (w==0){ float z = warp_max(sred[lane]); if (lane==0) bresM = z; }
        __syncthreads();
        m = bresM;
        float sum = 0.f;
        #pragma unroll
        for (int j=0;j<8;j++) sum += expf(sl[j]+bl[j]-m);
        sum = warp_sum(sum);
        if (lane==0) sred[w]=sum;
        __syncthreads();
        if (w==0){ float z = warp_sum(sred[lane]); if (lane==0) bresS = z; }
        __syncthreads();
        a = logk - (logf(bresS) + m);
        #pragma unroll
        for (int j=0;j<8;j++) bl[j] = -fmaxf(sl[j]+a, 0.f);
    }
    #pragma unroll
    for (int j=0;j<8;j++){
        int i = t*8+j;
        float sa = sl[j]+a;
        float val = (sa > 0.f) ? 1.0f : expf(sa);
        unsigned int vb = __float_as_uint(val);
        keys[i] = ((unsigned long long)vb << 32) |
                  (unsigned long long)(0xffffffffu - (unsigned)i);
    }
    __syncthreads();
    for (unsigned size=2; size<=N_; size<<=1){
        for (unsigned stride=size>>1; stride>0; stride>>=1){
            __syncthreads();
            for (unsigned q=t; q<N_/2; q+=1024){
                unsigned pos = 2*q - (q & (stride-1));
                unsigned par = pos + stride;
                bool asc = ((pos & size) == 0);
                unsigned long long a0=keys[pos], a1=keys[par];
                if ((a0 > a1) == asc){ keys[pos]=a1; keys[par]=a0; }
            }
        }
    }
    __syncthreads();
    int K = (route==0) ? NQ_ : NKV_;
    int* sel = idxbuf + (route*B_ + b)*NKV_;
    for (int j=t; j<K; j+=1024)
        sel[j] = (int)(0xffffffffu - (unsigned)(keys[N_-K+j] & 0xffffffffu));
}

// ---------------- 3. gather + rmsnorm (heavy branch) ----------------
__global__ __launch_bounds__(256) void gather_norm_kernel(
    const float* __restrict__ x, const float* __restrict__ gamma,
    const int* __restrict__ idxbuf, int route, int count, float* __restrict__ dst)
{
    int gi = blockIdx.x;
    int b = gi / count, j = gi % count;
    int rowidx = idxbuf[(route*B_ + b)*NKV_ + j];
    const float* xr = x + ((long long)b*N_ + rowidx)*D_;
    float* dr = dst + (long long)gi*D_;
    int t = threadIdx.x;
    float xv[4]; float ss=0.f;
    #pragma unroll
    for (int j4=0;j4<4;j4++){
        int i = t + j4*256;
        float v = xr[i]; xv[j4]=v; ss = fmaf(v,v,ss);
    }
    __shared__ float sred[8];
    __shared__ float bres;
    ss = warp_sum(ss);
    int w=t>>5, lane=t&31;
    if (lane==0) sred[w]=ss;
    __syncthreads();
    if (w==0){ float z = lane<8? sred[lane]:0.f; z = warp_sum(z); if (lane==0) bres=z; }
    __syncthreads();
    float inv = 32.0f / fmaxf(sqrtf(bres), 1e-12f);
    #pragma unroll
    for (int j4=0;j4<4;j4++){
        int i = t + j4*256;
        dr[i] = xv[j4]*inv*gamma[i];
    }
}

// ---------------- 4. tf32 tensor-core GEMM with register-prefetch pipeline ----------------
// C[M,N] = A[M,K] @ B[K,N]; BM=128, BN=128, BK=32, 256 threads (8 warps 4Mx2N).
__global__ __launch_bounds__(256) void tf32gemm_kernel(
    const float* __restrict__ A, const float* __restrict__ Bm, float* __restrict__ C,
    int M, int N, int K)
{
    __shared__ float As[128][36];
    __shared__ float Bs[32][132];
    int tid = threadIdx.x;
    int m0 = blockIdx.y*128, n0 = blockIdx.x*128;
    int warp = tid>>5, lane = tid&31;
    int wm = (warp&3)*32;
    int wn = (warp>>2)*64;
    int g = lane>>2, tig = lane&3;

    int arow = tid>>1, acol = (tid&1)*16;
    int brow = tid>>3, bcol = (tid&7)*16;

    float c[2][8][4];
    #pragma unroll
    for (int t=0;t<2;t++)
        #pragma unroll
        for (int u=0;u<8;u++)
            #pragma unroll
            for (int v=0;v<4;v++) c[t][u][v]=0.f;

    float4 av[4], bv[4];
    #pragma unroll
    for (int i=0;i<4;i++)
        av[i] = *(const float4*)(A + (long long)(m0+arow)*K + acol + 4*i);
    #pragma unroll
    for (int i=0;i<4;i++)
        bv[i] = *(const float4*)(Bm + (long long)brow*N + n0 + bcol + 4*i);

    int ntiles = K >> 5;
    for (int t0=0; t0<ntiles; t0++){
        __syncthreads();
        #pragma unroll
        for (int i=0;i<4;i++) *(float4*)&As[arow][acol+4*i] = av[i];
        #pragma unroll
        for (int i=0;i<4;i++) *(float4*)&Bs[brow][bcol+4*i] = bv[i];
        __syncthreads();
        if (t0+1 < ntiles){
            int k0 = (t0+1)<<5;
            #pragma unroll
            for (int i=0;i<4;i++)
                av[i] = *(const float4*)(A + (long long)(m0+arow)*K + k0 + acol + 4*i);
            #pragma unroll
            for (int i=0;i<4;i++)
                bv[i] = *(const float4*)(Bm + (long long)(k0+brow)*N + n0 + bcol + 4*i);
        }
        #pragma unroll
        for (int ks=0; ks<4; ks++){
            int kb = ks*8;
            uint32_t a[2][4], b[8][2];
            #pragma unroll
            for (int t=0;t<2;t++){
                int mr = wm + t*16 + g;
                a[t][0] = f2tf(As[mr  ][kb+tig  ]);
                a[t][1] = f2tf(As[mr+8][kb+tig  ]);
                a[t][2] = f2tf(As[mr  ][kb+tig+4]);
                a[t][3] = f2tf(As[mr+8][kb+tig+4]);
            }
            #pragma unroll
            for (int u=0;u<8;u++){
                int nc = wn + u*8 + g;
                b[u][0] = f2tf(Bs[kb+tig  ][nc]);
                b[u][1] = f2tf(Bs[kb+tig+4][nc]);
            }
            #pragma unroll
            for (int t=0;t<2;t++)
                #pragma unroll
                for (int u=0;u<8;u++)
                    asm volatile(
                        "mma.sync.aligned.m16n8k8.row.col.f32.tf32.tf32.f32 "
                        "{%0,%1,%2,%3},{%4,%5,%6,%7},{%8,%9},{%0,%1,%2,%3};"
                        : "+f"(c[t][u][0]), "+f"(c[t][u][1]),
                          "+f"(c[t][u][2]), "+f"(c[t][u][3])
                        : "r"(a[t][0]), "r"(a[t][1]), "r"(a[t][2]), "r"(a[t][3]),
                          "r"(b[u][0]), "r"(b[u][1]));
        }
    }
    #pragma unroll
    for (int t=0;t<2;t++){
        long long mr = m0 + wm + t*16 + g;
        #pragma unroll
        for (int u=0;u<8;u++){
            long long nc = n0 + wn + u*8 + 2*tig;
            *(float2*)&C[mr*N + nc]     = make_float2(c[t][u][0], c[t][u][1]);
            *(float2*)&C[(mr+8)*N + nc] = make_float2(c[t][u][2], c[t][u][3]);
        }
    }
}

// ---------------- 5/6. attention (spill-free: 2 threads per q-row, d split) ----------------
// mode 0: light windowed; mode 1: heavy. 256 threads.
template<int MODE>
__global__ __launch_bounds__(256) void attn_kernel(
    const float* __restrict__ Q, const float* __restrict__ KV, float* __restrict__ O)
{
    __shared__ float ks[32][72], vs[32][72];
    int bid = blockIdx.x;
    int t = threadIdx.x;
    int i = t >> 1;            // q row within 128-tile
    int hf = t & 1;            // d-half selector (interleaved 4-float chunks)
    long long qbase, kvbase;
    int h, kvlen, kvstride, voff;
    if (MODE == 0){            // bid = b*512 + w*8 + h
        h = bid & 7;
        int w = (bid >> 3) & 63;
        int b = bid >> 9;
        long long base_row = (long long)b*N_ + (long long)w*WIN_;
        qbase  = (base_row + i)*HID_ + h*DH_;
        kvbase = base_row*(2*HID_) + h*DH_;
        kvstride = 2*HID_; voff = HID_; kvlen = WIN_;
    } else {                   // bid = b*64 + h*8 + qt
        int qt = bid & 7;
        h  = (bid >> 3) & 7;
        int b  = bid >> 6;
        qbase  = ((long long)b*NQ_ + qt*128 + i)*HID_ + h*DH_;
        kvbase = (long long)b*NKV_*(2*HID_) + h*128;
        kvstride = 2*HID_; voff = 64; kvlen = NKV_;
    }
    // load q: positions d = 8*ii + 4*hf + c  (ii 0..7, c 0..3)
    const float* qp = Q + qbase;
    float4 qv[8];
    #pragma unroll
    for (int ii=0;ii<8;ii++){
        float4 v = *(const float4*)(qp + 8*ii + 4*hf);
        qv[ii] = make_float4(v.x*0.125f, v.y*0.125f, v.z*0.125f, v.w*0.125f);
    }
    float m = -INFINITY, l = 0.f;
    float4 acc[8];
    #pragma unroll
    for (int ii=0;ii<8;ii++) acc[ii]=make_float4(0.f,0.f,0.f,0.f);

    int r  = t >> 3;           // smem fill: 32 rows, 8 threads/row
    int cc = (t & 7) * 8;
    for (int t0=0; t0<kvlen; t0+=32){
        __syncthreads();
        {
            const float* kp = KV + kvbase + (long long)(t0 + r)*kvstride;
            const float* vp = kp + voff;
            *(float4*)&ks[r][cc]   = *(const float4*)(kp + cc);
            *(float4*)&ks[r][cc+4] = *(const float4*)(kp + cc + 4);
            *(float4*)&vs[r][cc]   = *(const float4*)(vp + cc);
            *(float4*)&vs[r][cc+4] = *(const float4*)(vp + cc + 4);
        }
        __syncthreads();
        float sj[32], tmx = -INFINITY;
        #pragma unroll
        for (int j=0;j<32;j++){
            float part = 0.f;
            #pragma unroll
            for (int ii=0;ii<8;ii++){
                float4 kk = *(const float4*)&ks[j][8*ii+4*hf];
                part = fmaf(qv[ii].x, kk.x, part);
                part = fmaf(qv[ii].y, kk.y, part);
                part = fmaf(qv[ii].z, kk.z, part);
                part = fmaf(qv[ii].w, kk.w, part);
            }
            float s = part + __shfl_xor_sync(0xffffffffu, part, 1);
            sj[j] = s; tmx = fmaxf(tmx, s);
        }
        float mn = fmaxf(m, tmx);
        float corr = __expf(m - mn);
        l *= corr;
        #pragma unroll
        for (int ii=0;ii<8;ii++){
            acc[ii].x*=corr; acc[ii].y*=corr; acc[ii].z*=corr; acc[ii].w*=corr;
        }
        #pragma unroll
        for (int j=0;j<32;j++){
            float pexp = __expf(sj[j]-mn);
            l += pexp;
            #pragma unroll
            for (int ii=0;ii<8;ii++){
                float4 vv = *(const float4*)&vs[j][8*ii+4*hf];
                acc[ii].x = fmaf(pexp, vv.x, acc[ii].x);
                acc[ii].y = fmaf(pexp, vv.y, acc[ii].y);
                acc[ii].z = fmaf(pexp, vv.z, acc[ii].z);
                acc[ii].w = fmaf(pexp, vv.w, acc[ii].w);
            }
        }
        m = mn;
    }
    float invl = 1.f/l;
    float* op = O + qbase;
    #pragma unroll
    for (int ii=0;ii<8;ii++){
        float4 o4 = make_float4(acc[ii].x*invl, acc[ii].y*invl,
                                acc[ii].z*invl, acc[ii].w*invl);
        *(float4*)(op + 8*ii + 4*hf) = o4;
    }
}

// ---------------- 7. transpose 1024x1024 ----------------
__global__ void transpose1024_kernel(const float* __restrict__ in, float* __restrict__ out)
{
    __shared__ float tile[32][33];
    int x = blockIdx.x*32 + threadIdx.x;
    int y = blockIdx.y*32 + threadIdx.y;
    tile[threadIdx.y][threadIdx.x] = in[(long long)y*1024 + x];
    __syncthreads();
    int x2 = blockIdx.y*32 + threadIdx.x;
    int y2 = blockIdx.x*32 + threadIdx.y;
    out[(long long)y2*1024 + x2] = tile[threadIdx.x][threadIdx.y];
}

// ---------------- 8. scatter-add heavy rows into output ----------------
__global__ __launch_bounds__(256) void scatter_add_kernel(
    float* __restrict__ out, const int* __restrict__ idxbuf, const float* __restrict__ hout)
{
    int gi = blockIdx.x;
    int b = gi >> 10, j = gi & 1023;
    int row = idxbuf[(0*B_ + b)*NKV_ + j];
    float* o = out + ((long long)b*N_ + row)*D_;
    const float* hs = hout + (long long)gi*D_;
    for (int c=threadIdx.x; c<D_; c+=256) o[c] += hs[c];
}

// ---------------- launch ----------------
extern "C" void kernel_launch(void* const* d_in, const int* in_sizes, int n_in,
                              void* d_out, int out_size)
{
    const float* x       = (const float*)d_in[0];
    const float* gamma_l = (const float*)d_in[1];
    const float* wq_l    = (const float*)d_in[2];
    const float* wkv_l   = (const float*)d_in[3];
    const float* wo_l    = (const float*)d_in[4];
    const float* tq      = (const float*)d_in[5];
    const float* tkv     = (const float*)d_in[6];
    const float* gamma_h = (const float*)d_in[7];
    const float* wq_h    = (const float*)d_in[8];
    const float* wkv_h   = (const float*)d_in[9];
    const float* wo_h    = (const float*)d_in[10];
    float* out = (float*)d_out;

    void *p;
    cudaGetSymbolAddress(&p, g_xn);   float* xn   = (float*)p;
    cudaGetSymbolAddress(&p, g_ql);   float* ql   = (float*)p;
    cudaGetSymbolAddress(&p, g_kvl);  float* kvl  = (float*)p;
    cudaGetSymbolAddress(&p, g_aol);  float* aol  = (float*)p;
    cudaGetSymbolAddress(&p, g_s);    float* sarr = (float*)p;
    cudaGetSymbolAddress(&p, g_keys); unsigned long long* keys = (unsigned long long*)p;
    cudaGetSymbolAddress(&p, g_idx);  int* idx    = (int*)p;
    cudaGetSymbolAddress(&p, g_xqn);  float* xqn  = (float*)p;
    cudaGetSymbolAddress(&p, g_ctxn); float* ctxn = (float*)p;
    cudaGetSymbolAddress(&p, g_qh);   float* qh   = (float*)p;
    cudaGetSymbolAddress(&p, g_kvh);  float* kvh  = (float*)p;
    cudaGetSymbolAddress(&p, g_aoh);  float* aoh  = (float*)p;
    cudaGetSymbolAddress(&p, g_hout); float* hout = (float*)p;
    cudaGetSymbolAddress(&p, g_wkvT); float* wkvT = (float*)p;

    // light path
    rmsnorm_route_kernel<<<BN_, 256>>>(x, gamma_l, tq, tkv, xn, sarr);
    tf32gemm_kernel<<<dim3(HID_/128, BN_/128), 256>>>(xn, wq_l,  ql,  BN_, HID_,   D_);
    tf32gemm_kernel<<<dim3(1024/128, BN_/128), 256>>>(xn, wkv_l, kvl, BN_, 2*HID_, D_);
    attn_kernel<0><<<B_*NW_*H_, 256>>>(ql, kvl, aol);
    tf32gemm_kernel<<<dim3(D_/128, BN_/128), 256>>>(aol, wo_l, out, BN_, D_, HID_);

    // routing
    route_select_kernel<<<8, 1024>>>(sarr, keys, idx);

    // heavy path
    gather_norm_kernel<<<B_*NQ_,  256>>>(x, gamma_h, idx, 0, NQ_,  xqn);
    gather_norm_kernel<<<B_*NKV_, 256>>>(x, gamma_h, idx, 1, NKV_, ctxn);
    transpose1024_kernel<<<dim3(32,32), dim3(32,32)>>>(wkv_h, wkvT);
    tf32gemm_kernel<<<dim3(HID_/128, (B_*NQ_)/128),  256>>>(xqn,  wq_h, qh,  B_*NQ_,  HID_,   D_);
    tf32gemm_kernel<<<dim3(1024/128, (B_*NKV_)/128), 256>>>(ctxn, wkvT, kvh, B_*NKV_, 2*HID_, D_);
    attn_kernel<1><<<B_*H_*(NQ_/128), 256>>>(qh, kvh, aoh);
    tf32gemm_kernel<<<dim3(D_/128, (B_*NQ_)/128), 256>>>(aoh, wo_h, hout, B_*NQ_, D_, HID_);
    scatter_add_kernel<<<B_*NQ_, 256>>>(out, idx, hout);
}

// round 13
// speedup vs baseline: 1.2252x; 1.1634x over previous
#include <cuda_runtime.h>
#include <math.h>
#include <stdint.h>

#define B_ 4
#define N_ 8192
#define D_ 1024
#define H_ 8
#define DH_ 64
#define HID_ 512
#define WIN_ 128
#define NW_ 64
#define NQ_ 1024
#define NKV_ 2048
#define BN_ (B_*N_)

// GEMM smem layout (2-stage double buffer, dynamic)
#define AS_STRIDE 36
#define BS_STRIDE 132
#define AS_SIZE (128*AS_STRIDE)
#define BS_SIZE (32*BS_STRIDE)
#define GEMM_SMEM_BYTES ((2*(AS_SIZE+BS_SIZE))*4)

// ---------------- scratch (device globals; no allocations allowed) ----------------
__device__ float g_xn  [(long long)BN_*D_];
__device__ float g_ql  [(long long)BN_*HID_];
__device__ float g_kvl [(long long)BN_*2*HID_];
__device__ float g_aol [(long long)BN_*HID_];
__device__ float g_s   [2*B_*N_];
__device__ unsigned long long g_keys[8*N_];
__device__ int   g_idx [2*B_*NKV_];
__device__ float g_xqn [B_*NQ_*D_];
__device__ float g_ctxn[B_*NKV_*D_];
__device__ float g_qh  [B_*NQ_*HID_];
__device__ float g_kvh [B_*NKV_*2*HID_];
__device__ float g_aoh [B_*NQ_*HID_];
__device__ float g_hout[B_*NQ_*D_];
__device__ float g_wkvT[D_*2*HID_];

// ---------------- helpers ----------------
__device__ __forceinline__ float warp_max(float v){
    #pragma unroll
    for (int o=16;o;o>>=1) v = fmaxf(v, __shfl_xor_sync(0xffffffffu, v, o));
    return v;
}
__device__ __forceinline__ float warp_sum(float v){
    #pragma unroll
    for (int o=16;o;o>>=1) v += __shfl_xor_sync(0xffffffffu, v, o);
    return v;
}
__device__ __forceinline__ uint32_t f2tf(float f){
    uint32_t u;
    asm("cvt.rna.tf32.f32 %0, %1;" : "=r"(u) : "f"(f));
    return u;
}
__device__ __forceinline__ void cp_async16(uint32_t smem_addr, const void* gptr){
    asm volatile("cp.async.cg.shared.global [%0], [%1], 16;\n"
                 :: "r"(smem_addr), "l"(gptr));
}
__device__ __forceinline__ void cp_commit(){
    asm volatile("cp.async.commit_group;\n");
}
__device__ __forceinline__ void cp_wait1(){
    asm volatile("cp.async.wait_group 1;\n");
}

// ---------------- 1. rmsnorm(x)*gamma_light + routing logits ----------------
__global__ __launch_bounds__(256) void rmsnorm_route_kernel(
    const float* __restrict__ x, const float* __restrict__ gamma,
    const float* __restrict__ tq, const float* __restrict__ tkv,
    float* __restrict__ xn, float* __restrict__ sarr)
{
    long long row = blockIdx.x;
    const float* xr = x + row*D_;
    int t = threadIdx.x;
    float xv[4]; float ss=0.f, dq=0.f, dk=0.f;
    #pragma unroll
    for (int j=0;j<4;j++){
        int i = t + j*256;
        float v = xr[i]; xv[j]=v;
        ss = fmaf(v,v,ss); dq = fmaf(v,tq[i],dq); dk = fmaf(v,tkv[i],dk);
    }
    __shared__ float sred[3][8];
    __shared__ float bres[3];
    ss = warp_sum(ss); dq = warp_sum(dq); dk = warp_sum(dk);
    int w = t>>5, lane = t&31;
    if (lane==0){ sred[0][w]=ss; sred[1][w]=dq; sred[2][w]=dk; }
    __syncthreads();
    if (w==0){
        float a = lane<8 ? sred[0][lane] : 0.f;
        float b = lane<8 ? sred[1][lane] : 0.f;
        float c = lane<8 ? sred[2][lane] : 0.f;
        a = warp_sum(a); b = warp_sum(b); c = warp_sum(c);
        if (lane==0){ bres[0]=a; bres[1]=b; bres[2]=c; }
    }
    __syncthreads();
    float norm = fmaxf(sqrtf(bres[0]), 1e-12f);
    float inv = 32.0f / norm;
    float* xo = xn + row*D_;
    #pragma unroll
    for (int j=0;j<4;j++){
        int i = t + j*256;
        xo[i] = xv[j]*inv*gamma[i];
    }
    if (t==0){
        int b = (int)(row >> 13);
        int n = (int)(row & (N_-1));
        sarr[(0*B_ + b)*N_ + n] = bres[1];
        sarr[(1*B_ + b)*N_ + n] = bres[2];
    }
}

// ---------------- 2. coor_descent (50 iters) + exact-tie top-k selection ----------------
__global__ __launch_bounds__(1024) void route_select_kernel(
    const float* __restrict__ sarr, unsigned long long* __restrict__ keysbuf,
    int* __restrict__ idxbuf)
{
    int p = blockIdx.x;            // 0..7 : route*4 + b
    int route = p >> 2, b = p & 3;
    const float* s = sarr + (route*B_ + b)*N_;
    unsigned long long* keys = keysbuf + (long long)p*N_;
    float logk = logf(route==0 ? 1152.0f : 2304.0f);
    int t = threadIdx.x;
    float sl[8], bl[8];
    #pragma unroll
    for (int j=0;j<8;j++){ sl[j] = s[t*8+j]; bl[j] = -sl[j]; }
    __shared__ float sred[32];
    __shared__ float bresM, bresS;
    int w = t>>5, lane = t&31;
    float a = 0.f;
    for (int it=0; it<50; it++){
        float m = -INFINITY;
        #pragma unroll
        for (int j=0;j<8;j++) m = fmaxf(m, sl[j]+bl[j]);
        m = warp_max(m);
        if (lane==0) sred[w]=m;
        __syncthreads();
        if (w==0){ float z = warp_max(sred[lane]); if (lane==0) bresM = z; }
        __syncthreads();
        m = bresM;
        float sum = 0.f;
        #pragma unroll
        for (int j=0;j<8;j++) sum += expf(sl[j]+bl[j]-m);
        sum = warp_sum(sum);
        if (lane==0) sred[w]=sum;
        __syncthreads();
        if (w==0){ float z = warp_sum(sred[lane]); if (lane==0) bresS = z; }
        __syncthreads();
        a = logk - (logf(bresS) + m);
        #pragma unroll
        for (int j=0;j<8;j++) bl[j] = -fmaxf(sl[j]+a, 0.f);
    }
    #pragma unroll
    for (int j=0;j<8;j++){
        int i = t*8+j;
        float sa = sl[j]+a;
        float val = (sa > 0.f) ? 1.0f : expf(sa);
        unsigned int vb = __float_as_uint(val);
        keys[i] = ((unsigned long long)vb << 32) |
                  (unsigned long long)(0xffffffffu - (unsigned)i);
    }
    __syncthreads();
    for (unsigned size=2; size<=N_; size<<=1){
        for (unsigned stride=size>>1; stride>0; stride>>=1){
            __syncthreads();
            for (unsigned q=t; q<N_/2; q+=1024){
                unsigned pos = 2*q - (q & (stride-1));
                unsigned par = pos + stride;
                bool asc = ((pos & size) == 0);
                unsigned long long a0=keys[pos], a1=keys[par];
                if ((a0 > a1) == asc){ keys[pos]=a1; keys[par]=a0; }
            }
        }
    }
    __syncthreads();
    int K = (route==0) ? NQ_ : NKV_;
    int* sel = idxbuf + (route*B_ + b)*NKV_;
    for (int j=t; j<K; j+=1024)
        sel[j] = (int)(0xffffffffu - (unsigned)(keys[N_-K+j] & 0xffffffffu));
}

// ---------------- 3. gather + rmsnorm (heavy branch) ----------------
__global__ __launch_bounds__(256) void gather_norm_kernel(
    const float* __restrict__ x, const float* __restrict__ gamma,
    const int* __restrict__ idxbuf, int route, int count, float* __restrict__ dst)
{
    int gi = blockIdx.x;
    int b = gi / count, j = gi % count;
    int rowidx = idxbuf[(route*B_ + b)*NKV_ + j];
    const float* xr = x + ((long long)b*N_ + rowidx)*D_;
    float* dr = dst + (long long)gi*D_;
    int t = threadIdx.x;
    float xv[4]; float ss=0.f;
    #pragma unroll
    for (int j4=0;j4<4;j4++){
        int i = t + j4*256;
        float v = xr[i]; xv[j4]=v; ss = fmaf(v,v,ss);
    }
    __shared__ float sred[8];
    __shared__ float bres;
    ss = warp_sum(ss);
    int w=t>>5, lane=t&31;
    if (lane==0) sred[w]=ss;
    __syncthreads();
    if (w==0){ float z = lane<8? sred[lane]:0.f; z = warp_sum(z); if (lane==0) bres=z; }
    __syncthreads();
    float inv = 32.0f / fmaxf(sqrtf(bres), 1e-12f);
    #pragma unroll
    for (int j4=0;j4<4;j4++){
        int i = t + j4*256;
        dr[i] = xv[j4]*inv*gamma[i];
    }
}

// ---------------- 4. tf32 tensor-core GEMM, 2-stage cp.async double buffer ----------------
// C[M,N] = A[M,K] @ B[K,N]; BM=128, BN=128, BK=32, 256 threads (8 warps 4Mx2N).
__global__ __launch_bounds__(256, 2) void tf32gemm_kernel(
    const float* __restrict__ A, const float* __restrict__ Bm, float* __restrict__ C,
    int M, int N, int K)
{
    extern __shared__ float sm[];
    float* As0 = sm;
    float* As1 = sm + AS_SIZE;
    float* Bs0 = sm + 2*AS_SIZE;
    float* Bs1 = sm + 2*AS_SIZE + BS_SIZE;

    int tid = threadIdx.x;
    int m0 = blockIdx.y*128, n0 = blockIdx.x*128;
    int warp = tid>>5, lane = tid&31;
    int wm = (warp&3)*32;
    int wn = (warp>>2)*64;
    int g = lane>>2, tig = lane&3;

    int arow = tid>>1, acol = (tid&1)*16;
    int brow = tid>>3, bcol = (tid&7)*16;

    const float* agp = A + (long long)(m0+arow)*K + acol;
    const float* bgp = Bm + (long long)brow*N + n0 + bcol;

    uint32_t asw[2], bsw[2];
    asw[0] = (uint32_t)__cvta_generic_to_shared(As0 + arow*AS_STRIDE + acol);
    asw[1] = (uint32_t)__cvta_generic_to_shared(As1 + arow*AS_STRIDE + acol);
    bsw[0] = (uint32_t)__cvta_generic_to_shared(Bs0 + brow*BS_STRIDE + bcol);
    bsw[1] = (uint32_t)__cvta_generic_to_shared(Bs1 + brow*BS_STRIDE + bcol);

    float c[2][8][4];
    #pragma unroll
    for (int t=0;t<2;t++)
        #pragma unroll
        for (int u=0;u<8;u++)
            #pragma unroll
            for (int v=0;v<4;v++) c[t][u][v]=0.f;

    int ntiles = K >> 5;
    // prologue: issue tiles 0 and 1
    #pragma unroll
    for (int i=0;i<4;i++) cp_async16(asw[0] + i*16, agp + 4*i);
    #pragma unroll
    for (int i=0;i<4;i++) cp_async16(bsw[0] + i*16, bgp + 4*i);
    cp_commit();
    #pragma unroll
    for (int i=0;i<4;i++) cp_async16(asw[1] + i*16, agp + 32 + 4*i);
    #pragma unroll
    for (int i=0;i<4;i++) cp_async16(bsw[1] + i*16, bgp + (long long)32*N + 4*i);
    cp_commit();

    for (int t0=0; t0<ntiles; t0++){
        cp_wait1();
        __syncthreads();
        int s = t0 & 1;
        const float* Acur = s ? As1 : As0;
        const float* Bcur = s ? Bs1 : Bs0;
        #pragma unroll
        for (int ks=0; ks<4; ks++){
            int kb = ks*8;
            uint32_t a[2][4], b[8][2];
            #pragma unroll
            for (int t=0;t<2;t++){
                int mr = wm + t*16 + g;
                a[t][0] = f2tf(Acur[mr*AS_STRIDE + kb+tig]);
                a[t][1] = f2tf(Acur[(mr+8)*AS_STRIDE + kb+tig]);
                a[t][2] = f2tf(Acur[mr*AS_STRIDE + kb+tig+4]);
                a[t][3] = f2tf(Acur[(mr+8)*AS_STRIDE + kb+tig+4]);
            }
            #pragma unroll
            for (int u=0;u<8;u++){
                int nc = wn + u*8 + g;
                b[u][0] = f2tf(Bcur[(kb+tig)*BS_STRIDE + nc]);
                b[u][1] = f2tf(Bcur[(kb+tig+4)*BS_STRIDE + nc]);
            }
            #pragma unroll
            for (int t=0;t<2;t++)
                #pragma unroll
                for (int u=0;u<8;u++)
                    asm volatile(
                        "mma.sync.aligned.m16n8k8.row.col.f32.tf32.tf32.f32 "
                        "{%0,%1,%2,%3},{%4,%5,%6,%7},{%8,%9},{%0,%1,%2,%3};"
                        : "+f"(c[t][u][0]), "+f"(c[t][u][1]),
                          "+f"(c[t][u][2]), "+f"(c[t][u][3])
                        : "r"(a[t][0]), "r"(a[t][1]), "r"(a[t][2]), "r"(a[t][3]),
                          "r"(b[u][0]), "r"(b[u][1]));
        }
        __syncthreads();
        if (t0+2 < ntiles){
            int k0 = (t0+2) << 5;
            #pragma unroll
            for (int i=0;i<4;i++) cp_async16(asw[s] + i*16, agp + k0 + 4*i);
            #pragma unroll
            for (int i=0;i<4;i++) cp_async16(bsw[s] + i*16, bgp + (long long)k0*N + 4*i);
        }
        cp_commit();
    }
    #pragma unroll
    for (int t=0;t<2;t++){
        long long mr = m0 + wm + t*16 + g;
        #pragma unroll
        for (int u=0;u<8;u++){
            long long nc = n0 + wn + u*8 + 2*tig;
            *(float2*)&C[mr*N + nc]     = make_float2(c[t][u][0], c[t][u][1]);
            *(float2*)&C[(mr+8)*N + nc] = make_float2(c[t][u][2], c[t][u][3]);
        }
    }
}

// ---------------- 5/6. attention (2 threads per q-row, d split; 2 blocks/SM) ----------------
template<int MODE>
__global__ __launch_bounds__(256, 2) void attn_kernel(
    const float* __restrict__ Q, const float* __restrict__ KV, float* __restrict__ O)
{
    __shared__ float ks[32][72], vs[32][72];
    int bid = blockIdx.x;
    int t = threadIdx.x;
    int i = t >> 1;            // q row within 128-tile
    int hf = t & 1;            // d-half selector (interleaved 4-float chunks)
    long long qbase, kvbase;
    int h, kvlen, kvstride, voff;
    if (MODE == 0){            // bid = b*512 + w*8 + h
        h = bid & 7;
        int w = (bid >> 3) & 63;
        int b = bid >> 9;
        long long base_row = (long long)b*N_ + (long long)w*WIN_;
        qbase  = (base_row + i)*HID_ + h*DH_;
        kvbase = base_row*(2*HID_) + h*DH_;
        kvstride = 2*HID_; voff = HID_; kvlen = WIN_;
    } else {                   // bid = b*64 + h*8 + qt
        int qt = bid & 7;
        h  = (bid >> 3) & 7;
        int b  = bid >> 6;
        qbase  = ((long long)b*NQ_ + qt*128 + i)*HID_ + h*DH_;
        kvbase = (long long)b*NKV_*(2*HID_) + h*128;
        kvstride = 2*HID_; voff = 64; kvlen = NKV_;
    }
    const float* qp = Q + qbase;
    float4 qv[8];
    #pragma unroll
    for (int ii=0;ii<8;ii++){
        float4 v = *(const float4*)(qp + 8*ii + 4*hf);
        qv[ii] = make_float4(v.x*0.125f, v.y*0.125f, v.z*0.125f, v.w*0.125f);
    }
    float m = -INFINITY, l = 0.f;
    float4 acc[8];
    #pragma unroll
    for (int ii=0;ii<8;ii++) acc[ii]=make_float4(0.f,0.f,0.f,0.f);

    int r  = t >> 3;           // smem fill: 32 rows, 8 threads/row
    int cc = (t & 7) * 8;
    for (int t0=0; t0<kvlen; t0+=32){
        __syncthreads();
        {
            const float* kp = KV + kvbase + (long long)(t0 + r)*kvstride;
            const float* vp = kp + voff;
            *(float4*)&ks[r][cc]   = *(const float4*)(kp + cc);
            *(float4*)&ks[r][cc+4] = *(const float4*)(kp + cc + 4);
            *(float4*)&vs[r][cc]   = *(const float4*)(vp + cc);
            *(float4*)&vs[r][cc+4] = *(const float4*)(vp + cc + 4);
        }
        __syncthreads();
        float sj[32], tmx = -INFINITY;
        #pragma unroll
        for (int j=0;j<32;j++){
            float part = 0.f;
            #pragma unroll
            for (int ii=0;ii<8;ii++){
                float4 kk = *(const float4*)&ks[j][8*ii+4*hf];
                part = fmaf(qv[ii].x, kk.x, part);
                part = fmaf(qv[ii].y, kk.y, part);
                part = fmaf(qv[ii].z, kk.z, part);
                part = fmaf(qv[ii].w, kk.w, part);
            }
            float s = part + __shfl_xor_sync(0xffffffffu, part, 1);
            sj[j] = s; tmx = fmaxf(tmx, s);
        }
        float mn = fmaxf(m, tmx);
        float corr = __expf(m - mn);
        l *= corr;
        #pragma unroll
        for (int ii=0;ii<8;ii++){
            acc[ii].x*=corr; acc[ii].y*=corr; acc[ii].z*=corr; acc[ii].w*=corr;
        }
        #pragma unroll
        for (int j=0;j<32;j++){
            float pexp = __expf(sj[j]-mn);
            l += pexp;
            #pragma unroll
            for (int ii=0;ii<8;ii++){
                float4 vv = *(const float4*)&vs[j][8*ii+4*hf];
                acc[ii].x = fmaf(pexp, vv.x, acc[ii].x);
                acc[ii].y = fmaf(pexp, vv.y, acc[ii].y);
                acc[ii].z = fmaf(pexp, vv.z, acc[ii].z);
                acc[ii].w = fmaf(pexp, vv.w, acc[ii].w);
            }
        }
        m = mn;
    }
    float invl = 1.f/l;
    float* op = O + qbase;
    #pragma unroll
    for (int ii=0;ii<8;ii++){
        float4 o4 = make_float4(acc[ii].x*invl, acc[ii].y*invl,
                                acc[ii].z*invl, acc[ii].w*invl);
        *(float4*)(op + 8*ii + 4*hf) = o4;
    }
}

// ---------------- 7. transpose 1024x1024 ----------------
__global__ void transpose1024_kernel(const float* __restrict__ in, float* __restrict__ out)
{
    __shared__ float tile[32][33];
    int x = blockIdx.x*32 + threadIdx.x;
    int y = blockIdx.y*32 + threadIdx.y;
    tile[threadIdx.y][threadIdx.x] = in[(long long)y*1024 + x];
    __syncthreads();
    int x2 = blockIdx.y*32 + threadIdx.x;
    int y2 = blockIdx.x*32 + threadIdx.y;
    out[(long long)y2*1024 + x2] = tile[threadIdx.x][threadIdx.y];
}

// ---------------- 8. scatter-add heavy rows into output ----------------
__global__ __launch_bounds__(256) void scatter_add_kernel(
    float* __restrict__ out, const int* __restrict__ idxbuf, const float* __restrict__ hout)
{
    int gi = blockIdx.x;
    int b = gi >> 10, j = gi & 1023;
    int row = idxbuf[(0*B_ + b)*NKV_ + j];
    float* o = out + ((long long)b*N_ + row)*D_;
    const float* hs = hout + (long long)gi*D_;
    for (int c=threadIdx.x; c<D_; c+=256) o[c] += hs[c];
}

// ---------------- launch ----------------
extern "C" void kernel_launch(void* const* d_in, const int* in_sizes, int n_in,
                              void* d_out, int out_size)
{
    const float* x       = (const float*)d_in[0];
    const float* gamma_l = (const float*)d_in[1];
    const float* wq_l    = (const float*)d_in[2];
    const float* wkv_l   = (const float*)d_in[3];
    const float* wo_l    = (const float*)d_in[4];
    const float* tq      = (const float*)d_in[5];
    const float* tkv     = (const float*)d_in[6];
    const float* gamma_h = (const float*)d_in[7];
    const float* wq_h    = (const float*)d_in[8];
    const float* wkv_h   = (const float*)d_in[9];
    const float* wo_h    = (const float*)d_in[10];
    float* out = (float*)d_out;

    void *p;
    cudaGetSymbolAddress(&p, g_xn);   float* xn   = (float*)p;
    cudaGetSymbolAddress(&p, g_ql);   float* ql   = (float*)p;
    cudaGetSymbolAddress(&p, g_kvl);  float* kvl  = (float*)p;
    cudaGetSymbolAddress(&p, g_aol);  float* aol  = (float*)p;
    cudaGetSymbolAddress(&p, g_s);    float* sarr = (float*)p;
    cudaGetSymbolAddress(&p, g_keys); unsigned long long* keys = (unsigned long long*)p;
    cudaGetSymbolAddress(&p, g_idx);  int* idx    = (int*)p;
    cudaGetSymbolAddress(&p, g_xqn);  float* xqn  = (float*)p;
    cudaGetSymbolAddress(&p, g_ctxn); float* ctxn = (float*)p;
    cudaGetSymbolAddress(&p, g_qh);   float* qh   = (float*)p;
    cudaGetSymbolAddress(&p, g_kvh);  float* kvh  = (float*)p;
    cudaGetSymbolAddress(&p, g_aoh);  float* aoh  = (float*)p;
    cudaGetSymbolAddress(&p, g_hout); float* hout = (float*)p;
    cudaGetSymbolAddress(&p, g_wkvT); float* wkvT = (float*)p;

    cudaFuncSetAttribute(tf32gemm_kernel,
                         cudaFuncAttributeMaxDynamicSharedMemorySize, GEMM_SMEM_BYTES);

    // light path
    rmsnorm_route_kernel<<<BN_, 256>>>(x, gamma_l, tq, tkv, xn, sarr);
    tf32gemm_kernel<<<dim3(HID_/128, BN_/128), 256, GEMM_SMEM_BYTES>>>(xn, wq_l,  ql,  BN_, HID_,   D_);
    tf32gemm_kernel<<<dim3(1024/128, BN_/128), 256, GEMM_SMEM_BYTES>>>(xn, wkv_l, kvl, BN_, 2*HID_, D_);
    attn_kernel<0><<<B_*NW_*H_, 256>>>(ql, kvl, aol);
    tf32gemm_kernel<<<dim3(D_/128, BN_/128), 256, GEMM_SMEM_BYTES>>>(aol, wo_l, out, BN_, D_, HID_);

    // routing
    route_select_kernel<<<8, 1024>>>(sarr, keys, idx);

    // heavy path
    gather_norm_kernel<<<B_*NQ_,  256>>>(x, gamma_h, idx, 0, NQ_,  xqn);
    gather_norm_kernel<<<B_*NKV_, 256>>>(x, gamma_h, idx, 1, NKV_, ctxn);
    transpose1024_kernel<<<dim3(32,32), dim3(32,32)>>>(wkv_h, wkvT);
    tf32gemm_kernel<<<dim3(HID_/128, (B_*NQ_)/128),  256, GEMM_SMEM_BYTES>>>(xqn,  wq_h, qh,  B_*NQ_,  HID_,   D_);
    tf32gemm_kernel<<<dim3(1024/128, (B_*NKV_)/128), 256, GEMM_SMEM_BYTES>>>(ctxn, wkvT, kvh, B_*NKV_, 2*HID_, D_);
    attn_kernel<1><<<B_*H_*(NQ_/128), 256>>>(qh, kvh, aoh);
    tf32gemm_kernel<<<dim3(D_/128, (B_*NQ_)/128), 256, GEMM_SMEM_BYTES>>>(aoh, wo_h, hout, B_*NQ_, D_, HID_);
    scatter_add_kernel<<<B_*NQ_, 256>>>(out, idx, hout);
}